// round 5
// baseline (speedup 1.0000x reference)
#include <cuda_runtime.h>
#include <cstdint>

#define Bb 64
#define Tt 1024
#define Vv 512
#define Ee 256
#define Uu 512
#define ZN 2048  // 4*U
#define NCTA 128

// ---------------- scratch (device globals; no runtime allocation) ----------
__device__ float g_A[(size_t)Tt * Bb * ZN];   // input-side preact [t][b][4U]
__device__ float g_H[(size_t)Tt * Uu * Bb];   // layer output stream [t][u][b]
__device__ float g_hbuf[2 * Uu * Bb];         // recurrent h, double buffered, [u][b]
__device__ unsigned g_cnt = 0;
__device__ unsigned g_gen = 0;

// ---------------- helpers ---------------------------------------------------
__device__ __forceinline__ unsigned long long pack2(float lo, float hi) {
    unsigned long long r;
    asm("mov.b64 %0, {%1, %2};"
        : "=l"(r) : "r"(__float_as_uint(lo)), "r"(__float_as_uint(hi)));
    return r;
}
__device__ __forceinline__ void unpack2(unsigned long long v, float& lo, float& hi) {
    unsigned int a, b;
    asm("mov.b64 {%0, %1}, %2;" : "=r"(a), "=r"(b) : "l"(v));
    lo = __uint_as_float(a);
    hi = __uint_as_float(b);
}
__device__ __forceinline__ void ffma2(unsigned long long& d, unsigned long long a,
                                      unsigned long long b) {
    asm("fma.rn.f32x2 %0, %1, %2, %0;" : "+l"(d) : "l"(a), "l"(b));
}
__device__ __forceinline__ unsigned ld_acq(const unsigned* p) {
    unsigned v;
    asm volatile("ld.acquire.gpu.global.u32 %0, [%1];" : "=r"(v) : "l"(p) : "memory");
    return v;
}
__device__ __forceinline__ void cp_async16(unsigned s, const void* g) {
    asm volatile("cp.async.cg.shared.global [%0], [%1], 16;" ::"r"(s), "l"(g)
                 : "memory");
}
__device__ __forceinline__ float fast_tanh(float x) {
    float y;
    asm("tanh.approx.f32 %0, %1;" : "=f"(y) : "f"(x));
    return y;
}
__device__ __forceinline__ float fast_sig(float x) {
    return __fdividef(1.f, 1.f + __expf(-x));
}

// ---------------- grid-wide barrier (all 128 CTAs resident) ----------------
__device__ __forceinline__ void grid_sync() {
    __threadfence();
    __syncthreads();
    if (threadIdx.x == 0) {
        unsigned g = ld_acq(&g_gen);
        unsigned arrived = atomicAdd(&g_cnt, 1);
        if (arrived == NCTA - 1) {
            atomicExch(&g_cnt, 0);
            __threadfence();
            atomicAdd(&g_gen, 1);
        } else {
            while (ld_acq(&g_gen) == g) {
            }
        }
    }
    __syncthreads();
}

// ---------------- generic SGEMM: C[M,N] = A[M,K] @ B[K,N] + bias -----------
// Register-prefetch pipelined: tile k0+16 is LDG'd into registers while tile
// k0 computes; only STS + 2 BAR are exposed per iteration.
// AMODE 1: A row m gathered from emb[tokens] (K=E); m = t*64+b
// AMODE 2: A from H laid out [t][k][b]; row m = t*64+b
// OMODE 0: C row-major [m][n], ldc = Ntot
// OMODE 1: logits permute: m=(t*64+b) -> C[b*T*V + t*V + n]
template <int AMODE, int OMODE>
__global__ void sgemm_kernel(const float* __restrict__ Ag,
                             const int* __restrict__ tokens,
                             const float* __restrict__ emb,
                             const float* __restrict__ Bg,
                             const float* __restrict__ bias,
                             float* __restrict__ C, int K, int Ntot) {
    __shared__ float As[16][128];
    __shared__ unsigned long long Bs[16][64];  // pre-duplicated f32x2
    const int tid = threadIdx.x;               // 256 threads
    const int tx = tid & 15;                   // n-group
    const int ty = tid >> 4;                   // m-group
    const int m0 = blockIdx.y * 128;
    const int n0 = blockIdx.x * 64;

    // per-thread load coordinates (A: two float4 chunks per tile)
    int a_m[2], a_k4[2];
    const float* a_base[2];
#pragma unroll
    for (int i = 0; i < 2; i++) {
        int idx = tid + i * 256;  // 0..511
        if (AMODE == 1) {
            a_m[i] = idx >> 2;            // 0..127
            a_k4[i] = (idx & 3) * 4;      // 0,4,8,12
            int gm = m0 + a_m[i];
            int tb = gm & (Bb - 1);
            int tt = gm >> 6;
            int tok = tokens[tb * Tt + tt];
            a_base[i] = emb + (size_t)tok * Ee + a_k4[i];
        } else {
            int k = idx >> 5;             // 0..15
            int m = (idx & 31) * 4;       // 0..124
            a_m[i] = m;
            a_k4[i] = k;
            int t = (m0 + m) >> 6;
            int b = m & 63;
            a_base[i] = Ag + ((size_t)t * K + k) * Bb + b;
        }
    }
    const int b_k = tid >> 4;
    const int b_n4 = (tid & 15) * 4;
    const float* b_base = Bg + (size_t)b_k * Ntot + n0 + b_n4;

    unsigned long long acc[4][4];
#pragma unroll
    for (int i = 0; i < 4; i++)
#pragma unroll
        for (int j = 0; j < 4; j++) acc[i][j] = 0ull;

    // prefetch tile 0
    float4 pa[2], pb;
#pragma unroll
    for (int i = 0; i < 2; i++) pa[i] = *(const float4*)a_base[i];
    pb = *(const float4*)b_base;

    for (int k0 = 0; k0 < K; k0 += 16) {
        // store prefetched tile to SMEM
#pragma unroll
        for (int i = 0; i < 2; i++) {
            if (AMODE == 1) {
                As[a_k4[i] + 0][a_m[i]] = pa[i].x;
                As[a_k4[i] + 1][a_m[i]] = pa[i].y;
                As[a_k4[i] + 2][a_m[i]] = pa[i].z;
                As[a_k4[i] + 3][a_m[i]] = pa[i].w;
            } else {
                *(float4*)&As[a_k4[i]][a_m[i]] = pa[i];
            }
        }
        {
            unsigned long long* d = &Bs[b_k][b_n4];
            d[0] = pack2(pb.x, pb.x);
            d[1] = pack2(pb.y, pb.y);
            d[2] = pack2(pb.z, pb.z);
            d[3] = pack2(pb.w, pb.w);
        }
        __syncthreads();

        // issue next tile's loads (latency hidden under compute below)
        if (k0 + 16 < K) {
            if (AMODE == 1) {
#pragma unroll
                for (int i = 0; i < 2; i++)
                    pa[i] = *(const float4*)(a_base[i] + (k0 + 16));
            } else {
#pragma unroll
                for (int i = 0; i < 2; i++)
                    pa[i] = *(const float4*)(a_base[i] + (size_t)(k0 + 16) * Bb);
            }
            pb = *(const float4*)(b_base + (size_t)(k0 + 16) * Ntot);
        }

#pragma unroll
        for (int kk = 0; kk < 16; kk++) {
            ulonglong2 a01 = *(ulonglong2*)&As[kk][ty * 8];
            ulonglong2 a23 = *(ulonglong2*)&As[kk][ty * 8 + 4];
            ulonglong2 b01 = *(ulonglong2*)&Bs[kk][tx * 4];
            ulonglong2 b23 = *(ulonglong2*)&Bs[kk][tx * 4 + 2];
            unsigned long long ap0 = a01.x, ap1 = a01.y, ap2 = a23.x, ap3 = a23.y;
            ffma2(acc[0][0], ap0, b01.x); ffma2(acc[0][1], ap0, b01.y);
            ffma2(acc[0][2], ap0, b23.x); ffma2(acc[0][3], ap0, b23.y);
            ffma2(acc[1][0], ap1, b01.x); ffma2(acc[1][1], ap1, b01.y);
            ffma2(acc[1][2], ap1, b23.x); ffma2(acc[1][3], ap1, b23.y);
            ffma2(acc[2][0], ap2, b01.x); ffma2(acc[2][1], ap2, b01.y);
            ffma2(acc[2][2], ap2, b23.x); ffma2(acc[2][3], ap2, b23.y);
            ffma2(acc[3][0], ap3, b01.x); ffma2(acc[3][1], ap3, b01.y);
            ffma2(acc[3][2], ap3, b23.x); ffma2(acc[3][3], ap3, b23.y);
        }
        __syncthreads();
    }
    // epilogue
#pragma unroll
    for (int mp = 0; mp < 4; mp++) {
#pragma unroll
        for (int ni = 0; ni < 4; ni++) {
            float f0, f1;
            unpack2(acc[mp][ni], f0, f1);
            int n = n0 + tx * 4 + ni;
            float bv = bias[n];
            int m = m0 + ty * 8 + mp * 2;
            if (OMODE == 0) {
                C[(size_t)m * Ntot + n] = f0 + bv;
                C[(size_t)(m + 1) * Ntot + n] = f1 + bv;
            } else {
                int t0 = m >> 6, b0 = m & 63;
                int t1 = (m + 1) >> 6, b1 = (m + 1) & 63;
                C[(size_t)b0 * Tt * Vv + (size_t)t0 * Vv + n] = f0 + bv;
                C[(size_t)b1 * Tt * Vv + (size_t)t1 * Vv + n] = f1 + bv;
            }
        }
    }
}

// ---------------- persistent LSTM layer kernel -----------------------------
// 128 CTAs x 256 threads, each CTA owns 4 units. SMEM: full h [k][b] (128KB),
// Wr slice duplicated to f32x2 (64KB), A staging za (4KB), z staging zb (4KB).
// h broadcast is staged in 4 cp.async chunks consumed progressively under the
// GEMM so only chunk 0's fill is exposed.
#define HS_F (Uu * Bb)          // 32768 floats
#define WDS_F (Uu * 16 * 2)     // 16384 floats (8192 ulonglong)
#define ZA_F (16 * Bb)          // 1024
#define ZB_F (16 * Bb)          // 1024
#define STEP_SMEM_BYTES ((HS_F + WDS_F + ZA_F + ZB_F) * 4)  // 204800

__global__ __launch_bounds__(256, 1) void lstm_layer_kernel(
    const float* __restrict__ A, const float* __restrict__ Wr,
    const int* __restrict__ lengths, float* __restrict__ hbuf,
    float* __restrict__ H) {
    extern __shared__ float sm[];
    float* hs = sm;                                             // [512][64]
    unsigned long long* wds = (unsigned long long*)(sm + HS_F); // [512][16]
    float* za = sm + HS_F + WDS_F;                              // [4][64][4]
    float* zb = za + ZA_F;                                      // [16][64]
    const int tid = threadIdx.x;
    const int u0 = blockIdx.x * 4;
    const unsigned hs_s = (unsigned)__cvta_generic_to_shared(hs);

    // stage Wr slice, duplicated into f32x2 pairs (once per layer)
#pragma unroll
    for (int i = 0; i < 8; i++) {
        int idx = tid + i * 256;    // 0..2047
        int k = idx >> 2;
        int g = idx & 3;
        float4 w = *(const float4*)(Wr + (size_t)k * ZN + g * Uu + u0);
        unsigned long long* d = &wds[k * 16 + g * 4];
        d[0] = pack2(w.x, w.x);
        d[1] = pack2(w.y, w.y);
        d[2] = pack2(w.z, w.z);
        d[3] = pack2(w.w, w.w);
    }

    const int n = tid & 15;      // GEMM column (g*4+uu)
    const int mG = tid >> 4;     // GEMM batch quad
    const int uu = tid >> 6;     // gate-phase unit 0..3
    const int b = tid & 63;      // gate-phase batch
    const int u = u0 + uu;
    const int len = lengths[b];
    float creg = 0.f, hreg = 0.f;

    for (int t = 0; t < Tt; t++) {
        // A slice: one float4/thread (4 units of one gate for one batch)
        float4 a4 = *(const float4*)(A + ((size_t)t * Bb + b) * ZN + uu * Uu + u0);

        float zi, zf, zg, zo;
        if (t == 0) {
            // h == 0: z = A only
            *(float4*)&za[(uu * 64 + b) * 4] = a4;
            __syncthreads();
            zi = za[(0 * 64 + b) * 4 + uu];
            zf = za[(1 * 64 + b) * 4 + uu];
            zg = za[(2 * 64 + b) * 4 + uu];
            zo = za[(3 * 64 + b) * 4 + uu];
        } else {
            // async-stage h in 4 chunks of 128 k-rows; consume progressively
            const float4* src = (const float4*)(hbuf + (size_t)(t & 1) * HS_F);
#pragma unroll
            for (int c = 0; c < 4; c++) {
#pragma unroll
                for (int j = 0; j < 8; j++) {
                    int idx = c * 2048 + tid + j * 256;
                    cp_async16(hs_s + (unsigned)idx * 16, src + idx);
                }
                asm volatile("cp.async.commit_group;" ::: "memory");
            }

            *(float4*)&za[(uu * 64 + b) * 4] = a4;

            unsigned long long acc0 = 0ull, acc1 = 0ull;
#pragma unroll
            for (int c = 0; c < 4; c++) {
                if (c == 0)
                    asm volatile("cp.async.wait_group 3;" ::: "memory");
                else if (c == 1)
                    asm volatile("cp.async.wait_group 2;" ::: "memory");
                else if (c == 2)
                    asm volatile("cp.async.wait_group 1;" ::: "memory");
                else
                    asm volatile("cp.async.wait_group 0;" ::: "memory");
                __syncthreads();
#pragma unroll 8
                for (int k = c * 128; k < (c + 1) * 128; k++) {
                    ulonglong2 h2 = *(ulonglong2*)&hs[k * 64 + mG * 4];
                    unsigned long long wv = wds[k * 16 + n];
                    ffma2(acc0, h2.x, wv);
                    ffma2(acc1, h2.y, wv);
                }
            }
            {
                float f0, f1, f2, f3;
                unpack2(acc0, f0, f1);
                unpack2(acc1, f2, f3);
                *(float4*)&zb[n * 64 + mG * 4] = make_float4(f0, f1, f2, f3);
            }
            __syncthreads();
            zi = zb[(0 * 4 + uu) * 64 + b] + za[(0 * 64 + b) * 4 + uu];
            zf = zb[(1 * 4 + uu) * 64 + b] + za[(1 * 64 + b) * 4 + uu];
            zg = zb[(2 * 4 + uu) * 64 + b] + za[(2 * 64 + b) * 4 + uu];
            zo = zb[(3 * 4 + uu) * 64 + b] + za[(3 * 64 + b) * 4 + uu];
        }

        float ig = fast_sig(zi);
        float fg = fast_sig(zf);
        float gv = fast_tanh(zg);
        float og = fast_sig(zo);
        float cn = fg * creg + ig * gv;
        float hn = og * fast_tanh(cn);

        bool msk = t < len;
        if (msk) {
            creg = cn;
            hreg = hn;
        }
        __stcg(&hbuf[(size_t)((t + 1) & 1) * HS_F + u * 64 + b], hreg);
        H[((size_t)t * Uu + u) * Bb + b] = msk ? hn : 0.f;

        grid_sync();
    }
}

// ---------------- host: enqueue the whole pipeline (8 graph nodes) ---------
extern "C" void kernel_launch(void* const* d_in, const int* in_sizes, int n_in,
                              void* d_out, int out_size) {
    const int* tokens = (const int*)d_in[0];
    const int* lengths = (const int*)d_in[1];
    const float* emb = (const float*)d_in[2];
    const float* Wk[3] = {(const float*)d_in[3], (const float*)d_in[6],
                          (const float*)d_in[9]};
    const float* Wr[3] = {(const float*)d_in[4], (const float*)d_in[7],
                          (const float*)d_in[10]};
    const float* bv[3] = {(const float*)d_in[5], (const float*)d_in[8],
                          (const float*)d_in[11]};
    const float* Wd = (const float*)d_in[12];
    const float* bd = (const float*)d_in[13];
    float* out = (float*)d_out;

    float *A, *H, *hbuf;
    cudaGetSymbolAddress((void**)&A, g_A);
    cudaGetSymbolAddress((void**)&H, g_H);
    cudaGetSymbolAddress((void**)&hbuf, g_hbuf);

    cudaFuncSetAttribute(lstm_layer_kernel,
                         cudaFuncAttributeMaxDynamicSharedMemorySize,
                         STEP_SMEM_BYTES);

    dim3 blk(256);
    // layer-0 input preactivation: A = emb[tokens] @ Wk0 + b0
    sgemm_kernel<1, 0><<<dim3(ZN / 64, (Bb * Tt) / 128), blk>>>(
        nullptr, tokens, emb, Wk[0], bv[0], A, Ee, ZN);

    for (int l = 0; l < 3; l++) {
        if (l > 0) {
            // A = H_{l-1} @ Wk_l + b_l   (H layout [t][u][b])
            sgemm_kernel<2, 0><<<dim3(ZN / 64, (Bb * Tt) / 128), blk>>>(
                H, nullptr, nullptr, Wk[l], bv[l], A, Uu, ZN);
        }
        lstm_layer_kernel<<<NCTA, 256, STEP_SMEM_BYTES>>>(A, Wr[l], lengths,
                                                          hbuf, H);
    }
    // logits = H_2 @ Wd + bd, permuted to [b][t][v]
    sgemm_kernel<2, 1><<<dim3(Vv / 64, (Bb * Tt) / 128), blk>>>(
        H, nullptr, nullptr, Wd, bd, out, Uu, Vv);
}

// round 8
// speedup vs baseline: 1.4179x; 1.4179x over previous
#include <cuda_runtime.h>
#include <cuda_fp16.h>
#include <cstdint>

#define Bb 64
#define Tt 1024
#define Vv 512
#define Ee 256
#define Uu 512
#define ZN 2048  // 4*U
#define NCTA 128

// ---------------- scratch (device globals; no runtime allocation) ----------
__device__ float g_A[(size_t)Tt * Bb * ZN];   // input-side preact [t][b][4U]
__device__ float g_H[(size_t)Tt * Uu * Bb];   // layer output stream [t][u][b] fp32
__device__ __half g_hbuf[2 * 2 * Bb * Uu];    // h split: [buf][plane hi/lo][b][u]
__device__ unsigned g_cnt = 0;
__device__ unsigned g_gen = 0;

// ---------------- helpers ---------------------------------------------------
__device__ __forceinline__ unsigned long long pack2(float lo, float hi) {
    unsigned long long r;
    asm("mov.b64 %0, {%1, %2};"
        : "=l"(r) : "r"(__float_as_uint(lo)), "r"(__float_as_uint(hi)));
    return r;
}
__device__ __forceinline__ void unpack2(unsigned long long v, float& lo, float& hi) {
    unsigned int a, b;
    asm("mov.b64 {%0, %1}, %2;" : "=r"(a), "=r"(b) : "l"(v));
    lo = __uint_as_float(a);
    hi = __uint_as_float(b);
}
__device__ __forceinline__ void ffma2(unsigned long long& d, unsigned long long a,
                                      unsigned long long b) {
    asm("fma.rn.f32x2 %0, %1, %2, %0;" : "+l"(d) : "l"(a), "l"(b));
}
__device__ __forceinline__ unsigned ld_acq(const unsigned* p) {
    unsigned v;
    asm volatile("ld.acquire.gpu.global.u32 %0, [%1];" : "=r"(v) : "l"(p) : "memory");
    return v;
}
__device__ __forceinline__ void cp_async16(unsigned s, const void* g) {
    asm volatile("cp.async.cg.shared.global [%0], [%1], 16;" ::"r"(s), "l"(g)
                 : "memory");
}
__device__ __forceinline__ float fast_tanh(float x) {
    float y;
    asm("tanh.approx.f32 %0, %1;" : "=f"(y) : "f"(x));
    return y;
}
__device__ __forceinline__ float fast_sig(float x) {
    return __fdividef(1.f, 1.f + __expf(-x));
}
__device__ __forceinline__ void mma16816(float& d0, float& d1, float& d2, float& d3,
                                         uint32_t a0, uint32_t a1, uint32_t a2,
                                         uint32_t a3, uint32_t b0, uint32_t b1) {
    asm volatile(
        "mma.sync.aligned.m16n8k16.row.col.f32.f16.f16.f32 "
        "{%0,%1,%2,%3}, {%4,%5,%6,%7}, {%8,%9}, {%0,%1,%2,%3};"
        : "+f"(d0), "+f"(d1), "+f"(d2), "+f"(d3)
        : "r"(a0), "r"(a1), "r"(a2), "r"(a3), "r"(b0), "r"(b1));
}

// ---------------- grid-wide barrier (all 128 CTAs resident) ----------------
__device__ __forceinline__ void grid_sync() {
    __threadfence();
    __syncthreads();
    if (threadIdx.x == 0) {
        unsigned g = ld_acq(&g_gen);
        unsigned arrived = atomicAdd(&g_cnt, 1);
        if (arrived == NCTA - 1) {
            atomicExch(&g_cnt, 0);
            __threadfence();
            atomicAdd(&g_gen, 1);
        } else {
            while (ld_acq(&g_gen) == g) {
            }
        }
    }
    __syncthreads();
}

// ---------------- generic SGEMM: C[M,N] = A[M,K] @ B[K,N] + bias -----------
// (verbatim R4 — verified at rel_err 2.55e-5)
// AMODE 1: A row m gathered from emb[tokens] (K=E); m = t*64+b
// AMODE 2: A from H laid out [t][k][b]; row m = t*64+b
// OMODE 0: C row-major [m][n]; OMODE 1: logits permute -> C[b][t][n]
template <int AMODE, int OMODE>
__global__ void sgemm_kernel(const float* __restrict__ Ag,
                             const int* __restrict__ tokens,
                             const float* __restrict__ emb,
                             const float* __restrict__ Bg,
                             const float* __restrict__ bias,
                             float* __restrict__ C, int K, int Ntot) {
    __shared__ float As[16][128];
    __shared__ unsigned long long Bs[16][64];  // pre-duplicated f32x2
    const int tid = threadIdx.x;               // 256 threads
    const int tx = tid & 15;
    const int ty = tid >> 4;
    const int m0 = blockIdx.y * 128;
    const int n0 = blockIdx.x * 64;

    int a_m[2], a_k4[2];
    const float* a_base[2];
#pragma unroll
    for (int i = 0; i < 2; i++) {
        int idx = tid + i * 256;  // 0..511
        if (AMODE == 1) {
            a_m[i] = idx >> 2;
            a_k4[i] = (idx & 3) * 4;
            int gm = m0 + a_m[i];
            int tb = gm & (Bb - 1);
            int tt = gm >> 6;
            int tok = tokens[tb * Tt + tt];
            a_base[i] = emb + (size_t)tok * Ee + a_k4[i];
        } else {
            int k = idx >> 5;
            int m = (idx & 31) * 4;
            a_m[i] = m;
            a_k4[i] = k;
            int t = (m0 + m) >> 6;
            int b = m & 63;
            a_base[i] = Ag + ((size_t)t * K + k) * Bb + b;
        }
    }
    const int b_k = tid >> 4;
    const int b_n4 = (tid & 15) * 4;
    const float* b_base = Bg + (size_t)b_k * Ntot + n0 + b_n4;

    unsigned long long acc[4][4];
#pragma unroll
    for (int i = 0; i < 4; i++)
#pragma unroll
        for (int j = 0; j < 4; j++) acc[i][j] = 0ull;

    float4 pa[2], pb;
#pragma unroll
    for (int i = 0; i < 2; i++) pa[i] = *(const float4*)a_base[i];
    pb = *(const float4*)b_base;

    for (int k0 = 0; k0 < K; k0 += 16) {
#pragma unroll
        for (int i = 0; i < 2; i++) {
            if (AMODE == 1) {
                As[a_k4[i] + 0][a_m[i]] = pa[i].x;
                As[a_k4[i] + 1][a_m[i]] = pa[i].y;
                As[a_k4[i] + 2][a_m[i]] = pa[i].z;
                As[a_k4[i] + 3][a_m[i]] = pa[i].w;
            } else {
                *(float4*)&As[a_k4[i]][a_m[i]] = pa[i];
            }
        }
        {
            unsigned long long* d = &Bs[b_k][b_n4];
            d[0] = pack2(pb.x, pb.x);
            d[1] = pack2(pb.y, pb.y);
            d[2] = pack2(pb.z, pb.z);
            d[3] = pack2(pb.w, pb.w);
        }
        __syncthreads();

        if (k0 + 16 < K) {
            if (AMODE == 1) {
#pragma unroll
                for (int i = 0; i < 2; i++)
                    pa[i] = *(const float4*)(a_base[i] + (k0 + 16));
            } else {
#pragma unroll
                for (int i = 0; i < 2; i++)
                    pa[i] = *(const float4*)(a_base[i] + (size_t)(k0 + 16) * Bb);
            }
            pb = *(const float4*)(b_base + (size_t)(k0 + 16) * Ntot);
        }

#pragma unroll
        for (int kk = 0; kk < 16; kk++) {
            ulonglong2 a01 = *(ulonglong2*)&As[kk][ty * 8];
            ulonglong2 a23 = *(ulonglong2*)&As[kk][ty * 8 + 4];
            ulonglong2 b01 = *(ulonglong2*)&Bs[kk][tx * 4];
            ulonglong2 b23 = *(ulonglong2*)&Bs[kk][tx * 4 + 2];
            unsigned long long ap0 = a01.x, ap1 = a01.y, ap2 = a23.x, ap3 = a23.y;
            ffma2(acc[0][0], ap0, b01.x); ffma2(acc[0][1], ap0, b01.y);
            ffma2(acc[0][2], ap0, b23.x); ffma2(acc[0][3], ap0, b23.y);
            ffma2(acc[1][0], ap1, b01.x); ffma2(acc[1][1], ap1, b01.y);
            ffma2(acc[1][2], ap1, b23.x); ffma2(acc[1][3], ap1, b23.y);
            ffma2(acc[2][0], ap2, b01.x); ffma2(acc[2][1], ap2, b01.y);
            ffma2(acc[2][2], ap2, b23.x); ffma2(acc[2][3], ap2, b23.y);
            ffma2(acc[3][0], ap3, b01.x); ffma2(acc[3][1], ap3, b01.y);
            ffma2(acc[3][2], ap3, b23.x); ffma2(acc[3][3], ap3, b23.y);
        }
        __syncthreads();
    }
#pragma unroll
    for (int mp = 0; mp < 4; mp++) {
#pragma unroll
        for (int ni = 0; ni < 4; ni++) {
            float f0, f1;
            unpack2(acc[mp][ni], f0, f1);
            int n = n0 + tx * 4 + ni;
            float bv = bias[n];
            int m = m0 + ty * 8 + mp * 2;
            if (OMODE == 0) {
                C[(size_t)m * Ntot + n] = f0 + bv;
                C[(size_t)(m + 1) * Ntot + n] = f1 + bv;
            } else {
                int t0 = m >> 6, b0 = m & 63;
                int t1 = (m + 1) >> 6, b1 = (m + 1) & 63;
                C[(size_t)b0 * Tt * Vv + (size_t)t0 * Vv + n] = f0 + bv;
                C[(size_t)b1 * Tt * Vv + (size_t)t1 * Vv + n] = f1 + bv;
            }
        }
    }
}

// ---------------- persistent LSTM layer kernel (split-fp16 HMMA) -----------
// z = A + h@Wr with h,Wr in split fp16 (hi+lo planes), 3-term mma -> fp32
// quality. SMEM: hs hi/lo planes (64 rows x 1040B each), Wt hi/lo planes
// (16 rows x 1040B each), za/zb fp32 staging.
#define HS_ROW_B 1040
#define HS_PLANE (64 * HS_ROW_B)              // 66560
#define WT_OFF (2 * HS_PLANE)                 // 133120
#define WT_ROW_H 520
#define WT_PLANE (16 * HS_ROW_B)              // 16640
#define ZA_OFF (WT_OFF + 2 * WT_PLANE)        // 166400
#define ZB_OFF (ZA_OFF + 4096)                // 170496
#define STEP_SMEM_BYTES (ZB_OFF + 4096)       // 174592

__global__ __launch_bounds__(256, 1) void lstm_layer_kernel(
    const float* __restrict__ A, const float* __restrict__ Wr,
    const int* __restrict__ lengths, __half* __restrict__ hbuf,
    float* __restrict__ H) {
    extern __shared__ char smc[];
    char* hsH = smc;                            // hi plane
    char* hsL = smc + HS_PLANE;                 // lo plane
    __half* WtH = (__half*)(smc + WT_OFF);
    __half* WtL = (__half*)(smc + WT_OFF + WT_PLANE);
    float* za = (float*)(smc + ZA_OFF);         // [4 gates][64 b][4 units]
    float* zb = (float*)(smc + ZB_OFF);         // [16 cols][64 b]
    const int tid = threadIdx.x;
    const int u0 = blockIdx.x * 4;
    const unsigned hsH_s = (unsigned)__cvta_generic_to_shared(hsH);
    const unsigned hsL_s = hsH_s + HS_PLANE;

    // prepack Wr slice -> hi/lo fp16 planes [n][k] (col n = gate*4 + unit)
    for (int i = tid; i < 16 * Uu; i += 256) {
        int n = i & 15, k = i >> 4;
        int gg = n >> 2, uup = n & 3;
        float w = Wr[(size_t)k * ZN + gg * Uu + u0 + uup];
        __half whi = __float2half(w);
        __half wlo = __float2half(w - __half2float(whi));
        WtH[n * WT_ROW_H + k] = whi;
        WtL[n * WT_ROW_H + k] = wlo;
    }

    const int lane = tid & 31, warp = tid >> 5;
    const int fg = lane >> 2, tg = lane & 3;
    const int mt = warp & 3, nt = warp >> 2;
    const int rA0 = mt * 16 + fg;
    const int nB = nt * 8 + fg;
    const int uu = tid >> 6;
    const int b = tid & 63;
    const int u = u0 + uu;
    const int len = lengths[b];
    float creg = 0.f, hreg = 0.f;

    for (int t = 0; t < Tt; t++) {
        float4 a4 = *(const float4*)(A + ((size_t)t * Bb + b) * ZN + uu * Uu + u0);

        float zi, zf, zg, zo;
        if (t == 0) {
            *(float4*)&za[(uu * 64 + b) * 4] = a4;
            __syncthreads();
            zi = za[(0 * 64 + b) * 4 + uu];
            zf = za[(1 * 64 + b) * 4 + uu];
            zg = za[(2 * 64 + b) * 4 + uu];
            zo = za[(3 * 64 + b) * 4 + uu];
        } else {
            // async-stage hi+lo h planes in 4 k-chunks; consume progressively
            const __half* srcH = hbuf + (size_t)(t & 1) * (2 * Bb * Uu);
            const __half* srcL = srcH + Bb * Uu;
#pragma unroll
            for (int c = 0; c < 4; c++) {
#pragma unroll
                for (int j = 0; j < 4; j++) {
                    int item = tid + j * 256;
                    int row = item >> 4;
                    int c16 = c * 16 + (item & 15);
                    cp_async16(hsH_s + (unsigned)(row * HS_ROW_B + c16 * 16),
                               srcH + row * Uu + c16 * 8);
                }
#pragma unroll
                for (int j = 0; j < 4; j++) {
                    int item = tid + j * 256;
                    int row = item >> 4;
                    int c16 = c * 16 + (item & 15);
                    cp_async16(hsL_s + (unsigned)(row * HS_ROW_B + c16 * 16),
                               srcL + row * Uu + c16 * 8);
                }
                asm volatile("cp.async.commit_group;" ::: "memory");
            }

            *(float4*)&za[(uu * 64 + b) * 4] = a4;

            float d0 = 0.f, d1 = 0.f, d2 = 0.f, d3 = 0.f;
#pragma unroll
            for (int c = 0; c < 4; c++) {
                if (c == 0)
                    asm volatile("cp.async.wait_group 3;" ::: "memory");
                else if (c == 1)
                    asm volatile("cp.async.wait_group 2;" ::: "memory");
                else if (c == 2)
                    asm volatile("cp.async.wait_group 1;" ::: "memory");
                else
                    asm volatile("cp.async.wait_group 0;" ::: "memory");
                __syncthreads();
#pragma unroll
                for (int kt = 0; kt < 8; kt++) {
                    int k0 = c * 128 + kt * 16;
                    const char* arH = hsH + rA0 * HS_ROW_B + (k0 + 2 * tg) * 2;
                    uint32_t ah0 = *(const uint32_t*)(arH);
                    uint32_t ah1 = *(const uint32_t*)(arH + 8 * HS_ROW_B);
                    uint32_t ah2 = *(const uint32_t*)(arH + 16);
                    uint32_t ah3 = *(const uint32_t*)(arH + 8 * HS_ROW_B + 16);
                    const char* arL = arH + HS_PLANE;
                    uint32_t al0 = *(const uint32_t*)(arL);
                    uint32_t al1 = *(const uint32_t*)(arL + 8 * HS_ROW_B);
                    uint32_t al2 = *(const uint32_t*)(arL + 16);
                    uint32_t al3 = *(const uint32_t*)(arL + 8 * HS_ROW_B + 16);
                    const __half* brH = WtH + nB * WT_ROW_H + k0 + 2 * tg;
                    uint32_t bh0 = *(const uint32_t*)(brH);
                    uint32_t bh1 = *(const uint32_t*)(brH + 8);
                    const __half* brL = WtL + nB * WT_ROW_H + k0 + 2 * tg;
                    uint32_t bl0 = *(const uint32_t*)(brL);
                    uint32_t bl1 = *(const uint32_t*)(brL + 8);
                    // 3-term split: hi*hi + lo*hi + hi*lo
                    mma16816(d0, d1, d2, d3, ah0, ah1, ah2, ah3, bh0, bh1);
                    mma16816(d0, d1, d2, d3, al0, al1, al2, al3, bh0, bh1);
                    mma16816(d0, d1, d2, d3, ah0, ah1, ah2, ah3, bl0, bl1);
                }
            }
            zb[(nt * 8 + 2 * tg) * 64 + mt * 16 + fg] = d0;
            zb[(nt * 8 + 2 * tg + 1) * 64 + mt * 16 + fg] = d1;
            zb[(nt * 8 + 2 * tg) * 64 + mt * 16 + fg + 8] = d2;
            zb[(nt * 8 + 2 * tg + 1) * 64 + mt * 16 + fg + 8] = d3;
            __syncthreads();
            zi = zb[(0 * 4 + uu) * 64 + b] + za[(0 * 64 + b) * 4 + uu];
            zf = zb[(1 * 4 + uu) * 64 + b] + za[(1 * 64 + b) * 4 + uu];
            zg = zb[(2 * 4 + uu) * 64 + b] + za[(2 * 64 + b) * 4 + uu];
            zo = zb[(3 * 4 + uu) * 64 + b] + za[(3 * 64 + b) * 4 + uu];
        }

        float ig = fast_sig(zi);
        float fg2 = fast_sig(zf);
        float gv = fast_tanh(zg);
        float og = fast_sig(zo);
        float cn = fg2 * creg + ig * gv;
        float hn = og * fast_tanh(cn);

        bool msk = t < len;
        if (msk) {
            creg = cn;
            hreg = hn;
        }
        // split h for next step
        {
            __half hhi = __float2half(hreg);
            __half hlo = __float2half(hreg - __half2float(hhi));
            size_t base = (size_t)((t + 1) & 1) * (2 * Bb * Uu) + b * Uu + u;
            hbuf[base] = hhi;
            hbuf[base + Bb * Uu] = hlo;
        }
        H[((size_t)t * Uu + u) * Bb + b] = msk ? hn : 0.f;

        grid_sync();
    }
}

// ---------------- host: enqueue the whole pipeline (8 graph nodes) ---------
extern "C" void kernel_launch(void* const* d_in, const int* in_sizes, int n_in,
                              void* d_out, int out_size) {
    const int* tokens = (const int*)d_in[0];
    const int* lengths = (const int*)d_in[1];
    const float* emb = (const float*)d_in[2];
    const float* Wk[3] = {(const float*)d_in[3], (const float*)d_in[6],
                          (const float*)d_in[9]};
    const float* Wr[3] = {(const float*)d_in[4], (const float*)d_in[7],
                          (const float*)d_in[10]};
    const float* bv[3] = {(const float*)d_in[5], (const float*)d_in[8],
                          (const float*)d_in[11]};
    const float* Wd = (const float*)d_in[12];
    const float* bd = (const float*)d_in[13];
    float* out = (float*)d_out;

    float *A, *H;
    __half* hbuf;
    cudaGetSymbolAddress((void**)&A, g_A);
    cudaGetSymbolAddress((void**)&H, g_H);
    cudaGetSymbolAddress((void**)&hbuf, g_hbuf);

    cudaFuncSetAttribute(lstm_layer_kernel,
                         cudaFuncAttributeMaxDynamicSharedMemorySize,
                         STEP_SMEM_BYTES);

    dim3 blk(256);
    // layer-0 input preactivation: A = emb[tokens] @ Wk0 + b0
    sgemm_kernel<1, 0><<<dim3(ZN / 64, (Bb * Tt) / 128), blk>>>(
        nullptr, tokens, emb, Wk[0], bv[0], A, Ee, ZN);

    for (int l = 0; l < 3; l++) {
        if (l > 0) {
            // A = H_{l-1} @ Wk_l + b_l   (H layout [t][u][b])
            sgemm_kernel<2, 0><<<dim3(ZN / 64, (Bb * Tt) / 128), blk>>>(
                H, nullptr, nullptr, Wk[l], bv[l], A, Uu, ZN);
        }
        lstm_layer_kernel<<<NCTA, 256, STEP_SMEM_BYTES>>>(A, Wr[l], lengths,
                                                          hbuf, H);
    }
    // logits = H_2 @ Wd + bd, permuted to [b][t][v]
    sgemm_kernel<2, 1><<<dim3(Vv / 64, (Bb * Tt) / 128), blk>>>(
        H, nullptr, nullptr, Wd, bd, out, Uu, Vv);
}

// round 9
// speedup vs baseline: 1.8367x; 1.2954x over previous
#include <cuda_runtime.h>
#include <cuda_fp16.h>
#include <cstdint>

#define Bb 64
#define Tt 1024
#define Vv 512
#define Ee 256
#define Uu 512
#define ZN 2048  // 4*U
#define NCTA 128

// ---------------- scratch (device globals; no runtime allocation) ----------
__device__ float g_A[(size_t)Tt * Bb * ZN];   // input-side preact [t][b][4U]
__device__ float g_H[(size_t)Tt * Bb * Uu];   // layer stream fp32 [t][b][u] (row-major MxK)
__device__ __half g_hbuf[2 * 2 * Bb * Uu];    // h split: [buf][plane hi/lo][b][u]
__device__ unsigned g_leaf[8 * 32];           // 8 leaf counters, 128B apart
__device__ unsigned g_root[32];               // root counter (padded line)
__device__ unsigned g_gen = 0;

// ---------------- helpers ---------------------------------------------------
__device__ __forceinline__ unsigned ld_acq(const unsigned* p) {
    unsigned v;
    asm volatile("ld.acquire.gpu.global.u32 %0, [%1];" : "=r"(v) : "l"(p) : "memory");
    return v;
}
__device__ __forceinline__ void cp_async16(unsigned s, const void* g) {
    asm volatile("cp.async.cg.shared.global [%0], [%1], 16;" ::"r"(s), "l"(g)
                 : "memory");
}
__device__ __forceinline__ float fast_tanh(float x) {
    float y;
    asm("tanh.approx.f32 %0, %1;" : "=f"(y) : "f"(x));
    return y;
}
__device__ __forceinline__ float fast_sig(float x) {
    return __fdividef(1.f, 1.f + __expf(-x));
}
__device__ __forceinline__ void mma16816(float& d0, float& d1, float& d2, float& d3,
                                         uint32_t a0, uint32_t a1, uint32_t a2,
                                         uint32_t a3, uint32_t b0, uint32_t b1) {
    asm volatile(
        "mma.sync.aligned.m16n8k16.row.col.f32.f16.f16.f32 "
        "{%0,%1,%2,%3}, {%4,%5,%6,%7}, {%8,%9}, {%0,%1,%2,%3};"
        : "+f"(d0), "+f"(d1), "+f"(d2), "+f"(d3)
        : "r"(a0), "r"(a1), "r"(a2), "r"(a3), "r"(b0), "r"(b1));
}

// ---------------- two-level grid barrier (128 resident CTAs) ---------------
// 8 leaf counters x 16 CTAs, then a root counter; only the 128th arrival
// bumps g_gen, so gen is stable within an epoch (entry read == gen_t).
// Counters are monotonic (epoch via pos&15 / r&7): no reset races across
// steps, layer launches, or graph replays.
__device__ __forceinline__ void grid_sync(int bid) {
    __threadfence();
    __syncthreads();
    if (threadIdx.x == 0) {
        unsigned g = ld_acq(&g_gen);
        unsigned pos = atomicAdd(&g_leaf[(bid & 7) * 32], 1);
        if ((pos & 15) == 15) {              // last of this leaf's 16
            unsigned r = atomicAdd(&g_root[0], 1);
            if ((r & 7) == 7) {              // last leaf -> release
                __threadfence();
                atomicAdd(&g_gen, 1);
            }
        }
        while (ld_acq(&g_gen) == g) {
        }
    }
    __syncthreads();
}

// ---------------- split-fp16 HMMA GEMM: C = A @ B + bias -------------------
// A,B fp32 sources split to hi/lo fp16 planes at staging; 3-term mma
// (Hi*Hi + Lo*Hi + Hi*Lo) with fp32 accum == fp32-quality product.
// CTA tile 128m x 64n, k-step 32, 8 warps (warp = 16m x 64n).
// AMODE 1: A row m gathered from emb[tokens] (K=E); m = t*64+b
// AMODE 2: A = fp32 row-major [m][K] (the H stream)
// OMODE 0: C row-major [m][n]; OMODE 1: logits permute -> C[b][t][n]
template <int AMODE, int OMODE>
__global__ __launch_bounds__(256) void hgemm_kernel(
    const float* __restrict__ Ag, const int* __restrict__ tokens,
    const float* __restrict__ emb, const float* __restrict__ Bg,
    const float* __restrict__ bias, float* __restrict__ C, int K, int Ntot) {
    __shared__ __half AsH[128][40];  // 32 data halves + 8 pad (80B stride)
    __shared__ __half AsL[128][40];
    __shared__ __half BsH[64][40];   // Bs[n][k]
    __shared__ __half BsL[64][40];
    const int tid = threadIdx.x;
    const int m0 = blockIdx.y * 128;
    const int n0 = blockIdx.x * 64;
    const int lane = tid & 31, warp = tid >> 5;
    const int fg = lane >> 2, tg = lane & 3;

    // A staging: 4 float4 per thread (128 rows x 32 k fp32)
    int a_row[4], a_c4[4];
    const float* a_base[4];
#pragma unroll
    for (int i = 0; i < 4; i++) {
        int s = tid + i * 256;            // 0..1023
        a_row[i] = s >> 3;                // 0..127
        a_c4[i] = (s & 7) * 4;            // 0..28
        if (AMODE == 1) {
            int gm = m0 + a_row[i];
            int tb = gm & (Bb - 1);
            int tt = gm >> 6;
            int tok = tokens[tb * Tt + tt];
            a_base[i] = emb + (size_t)tok * Ee + a_c4[i];
        } else {
            a_base[i] = Ag + (size_t)(m0 + a_row[i]) * K + a_c4[i];
        }
    }
    // B staging: 2 float4 per thread (32 k x 64 n fp32)
    int b_kk[2], b_n4[2];
    const float* b_base[2];
#pragma unroll
    for (int i = 0; i < 2; i++) {
        int s = tid + i * 256;            // 0..511
        b_kk[i] = s >> 4;                 // 0..31
        b_n4[i] = (s & 15) * 4;
        b_base[i] = Bg + (size_t)b_kk[i] * Ntot + n0 + b_n4[i];
    }

    float acc[8][4];
#pragma unroll
    for (int j = 0; j < 8; j++)
#pragma unroll
        for (int q = 0; q < 4; q++) acc[j][q] = 0.f;

    float4 pa[4], pb[2];
#pragma unroll
    for (int i = 0; i < 4; i++) pa[i] = *(const float4*)a_base[i];
#pragma unroll
    for (int i = 0; i < 2; i++) pb[i] = *(const float4*)b_base[i];

    for (int k0 = 0; k0 < K; k0 += 32) {
        // ---- split-store prefetched tiles to SMEM ----
#pragma unroll
        for (int i = 0; i < 4; i++) {
            float4 v = pa[i];
            __half2 h01 = __floats2half2_rn(v.x, v.y);
            __half2 h23 = __floats2half2_rn(v.z, v.w);
            float2 f01 = __half22float2(h01);
            float2 f23 = __half22float2(h23);
            __half2 l01 = __floats2half2_rn(v.x - f01.x, v.y - f01.y);
            __half2 l23 = __floats2half2_rn(v.z - f23.x, v.w - f23.y);
            *(__half2*)&AsH[a_row[i]][a_c4[i]] = h01;
            *(__half2*)&AsH[a_row[i]][a_c4[i] + 2] = h23;
            *(__half2*)&AsL[a_row[i]][a_c4[i]] = l01;
            *(__half2*)&AsL[a_row[i]][a_c4[i] + 2] = l23;
        }
#pragma unroll
        for (int i = 0; i < 2; i++) {
            float vv[4] = {pb[i].x, pb[i].y, pb[i].z, pb[i].w};
#pragma unroll
            for (int q = 0; q < 4; q++) {
                int n = b_n4[i] + q;
                __half h = __float2half(vv[q]);
                BsH[n][b_kk[i]] = h;
                BsL[n][b_kk[i]] = __float2half(vv[q] - __half2float(h));
            }
        }
        __syncthreads();

        // ---- prefetch next tile ----
        if (k0 + 32 < K) {
#pragma unroll
            for (int i = 0; i < 4; i++)
                pa[i] = *(const float4*)(a_base[i] + (k0 + 32));
#pragma unroll
            for (int i = 0; i < 2; i++)
                pb[i] = *(const float4*)(b_base[i] + (size_t)(k0 + 32) * Ntot);
        }

        // ---- 3-term split mma over the 32-k tile ----
#pragma unroll
        for (int k16 = 0; k16 < 2; k16++) {
            const __half* arH = &AsH[warp * 16 + fg][k16 * 16 + 2 * tg];
            uint32_t ah0 = *(const uint32_t*)arH;
            uint32_t ah1 = *(const uint32_t*)(arH + 8 * 40);
            uint32_t ah2 = *(const uint32_t*)(arH + 8);
            uint32_t ah3 = *(const uint32_t*)(arH + 8 * 40 + 8);
            const __half* arL = &AsL[warp * 16 + fg][k16 * 16 + 2 * tg];
            uint32_t al0 = *(const uint32_t*)arL;
            uint32_t al1 = *(const uint32_t*)(arL + 8 * 40);
            uint32_t al2 = *(const uint32_t*)(arL + 8);
            uint32_t al3 = *(const uint32_t*)(arL + 8 * 40 + 8);
#pragma unroll
            for (int j = 0; j < 8; j++) {
                const __half* brH = &BsH[j * 8 + fg][k16 * 16 + 2 * tg];
                uint32_t bh0 = *(const uint32_t*)brH;
                uint32_t bh1 = *(const uint32_t*)(brH + 8);
                const __half* brL = &BsL[j * 8 + fg][k16 * 16 + 2 * tg];
                uint32_t bl0 = *(const uint32_t*)brL;
                uint32_t bl1 = *(const uint32_t*)(brL + 8);
                mma16816(acc[j][0], acc[j][1], acc[j][2], acc[j][3],
                         ah0, ah1, ah2, ah3, bh0, bh1);
                mma16816(acc[j][0], acc[j][1], acc[j][2], acc[j][3],
                         al0, al1, al2, al3, bh0, bh1);
                mma16816(acc[j][0], acc[j][1], acc[j][2], acc[j][3],
                         ah0, ah1, ah2, ah3, bl0, bl1);
            }
        }
        __syncthreads();
    }

    // ---- epilogue ----
    const int rowA = m0 + warp * 16 + fg;
#pragma unroll
    for (int j = 0; j < 8; j++) {
        int col = n0 + j * 8 + 2 * tg;
        float bv0 = bias[col], bv1 = bias[col + 1];
        float r0 = acc[j][0] + bv0, r1 = acc[j][1] + bv1;
        float r2 = acc[j][2] + bv0, r3 = acc[j][3] + bv1;
        if (OMODE == 0) {
            *(float2*)&C[(size_t)rowA * Ntot + col] = make_float2(r0, r1);
            *(float2*)&C[(size_t)(rowA + 8) * Ntot + col] = make_float2(r2, r3);
        } else {
            int t0 = rowA >> 6, b0 = rowA & 63;
            int t1 = (rowA + 8) >> 6, b1 = (rowA + 8) & 63;
            *(float2*)&C[(size_t)b0 * Tt * Vv + (size_t)t0 * Vv + col] =
                make_float2(r0, r1);
            *(float2*)&C[(size_t)b1 * Tt * Vv + (size_t)t1 * Vv + col] =
                make_float2(r2, r3);
        }
    }
}

// ---------------- persistent LSTM layer kernel (split-fp16 HMMA) -----------
#define HS_ROW_B 1040
#define HS_PLANE (64 * HS_ROW_B)
#define WT_OFF (2 * HS_PLANE)
#define WT_ROW_H 520
#define WT_PLANE (16 * HS_ROW_B)
#define ZA_OFF (WT_OFF + 2 * WT_PLANE)
#define ZB_OFF (ZA_OFF + 4096)
#define STEP_SMEM_BYTES (ZB_OFF + 4096)

__global__ __launch_bounds__(256, 1) void lstm_layer_kernel(
    const float* __restrict__ A, const float* __restrict__ Wr,
    const int* __restrict__ lengths, __half* __restrict__ hbuf,
    float* __restrict__ H) {
    extern __shared__ char smc[];
    char* hsH = smc;
    __half* WtH = (__half*)(smc + WT_OFF);
    __half* WtL = (__half*)(smc + WT_OFF + WT_PLANE);
    float* za = (float*)(smc + ZA_OFF);
    float* zb = (float*)(smc + ZB_OFF);
    const int tid = threadIdx.x;
    const int bid = blockIdx.x;
    const int u0 = bid * 4;
    const unsigned hsH_s = (unsigned)__cvta_generic_to_shared(hsH);
    const unsigned hsL_s = hsH_s + HS_PLANE;

    // prepack Wr slice -> hi/lo fp16 planes [n][k] (col n = gate*4 + unit)
    for (int i = tid; i < 16 * Uu; i += 256) {
        int n = i & 15, k = i >> 4;
        int gg = n >> 2, uup = n & 3;
        float w = Wr[(size_t)k * ZN + gg * Uu + u0 + uup];
        __half whi = __float2half(w);
        WtH[n * WT_ROW_H + k] = whi;
        WtL[n * WT_ROW_H + k] = __float2half(w - __half2float(whi));
    }

    const int lane = tid & 31, warp = tid >> 5;
    const int fg = lane >> 2, tg = lane & 3;
    const int mt = warp & 3, nt = warp >> 2;
    const int rA0 = mt * 16 + fg;
    const int nB = nt * 8 + fg;
    const int uu = tid >> 6;
    const int b = tid & 63;
    const int u = u0 + uu;
    const int len = lengths[b];
    float creg = 0.f, hreg = 0.f;

    // prefetch A(0)
    float4 a4 = *(const float4*)(A + ((size_t)0 * Bb + b) * ZN + uu * Uu + u0);

    for (int t = 0; t < Tt; t++) {
        float zi, zf, zg, zo;
        if (t == 0) {
            *(float4*)&za[(uu * 64 + b) * 4] = a4;
            __syncthreads();
            zi = za[(0 * 64 + b) * 4 + uu];
            zf = za[(1 * 64 + b) * 4 + uu];
            zg = za[(2 * 64 + b) * 4 + uu];
            zo = za[(3 * 64 + b) * 4 + uu];
        } else {
            // async-stage hi+lo h planes in 4 k-chunks; consume progressively
            const __half* srcH = hbuf + (size_t)(t & 1) * (2 * Bb * Uu);
            const __half* srcL = srcH + Bb * Uu;
#pragma unroll
            for (int c = 0; c < 4; c++) {
#pragma unroll
                for (int j = 0; j < 4; j++) {
                    int item = tid + j * 256;
                    int row = item >> 4;
                    int c16 = c * 16 + (item & 15);
                    cp_async16(hsH_s + (unsigned)(row * HS_ROW_B + c16 * 16),
                               srcH + row * Uu + c16 * 8);
                }
#pragma unroll
                for (int j = 0; j < 4; j++) {
                    int item = tid + j * 256;
                    int row = item >> 4;
                    int c16 = c * 16 + (item & 15);
                    cp_async16(hsL_s + (unsigned)(row * HS_ROW_B + c16 * 16),
                               srcL + row * Uu + c16 * 8);
                }
                asm volatile("cp.async.commit_group;" ::: "memory");
            }

            *(float4*)&za[(uu * 64 + b) * 4] = a4;

            float d0 = 0.f, d1 = 0.f, d2 = 0.f, d3 = 0.f;
#pragma unroll
            for (int c = 0; c < 4; c++) {
                if (c == 0)
                    asm volatile("cp.async.wait_group 3;" ::: "memory");
                else if (c == 1)
                    asm volatile("cp.async.wait_group 2;" ::: "memory");
                else if (c == 2)
                    asm volatile("cp.async.wait_group 1;" ::: "memory");
                else
                    asm volatile("cp.async.wait_group 0;" ::: "memory");
                __syncthreads();
#pragma unroll
                for (int kt = 0; kt < 8; kt++) {
                    int k0 = c * 128 + kt * 16;
                    const char* arH = hsH + rA0 * HS_ROW_B + (k0 + 2 * tg) * 2;
                    uint32_t ah0 = *(const uint32_t*)(arH);
                    uint32_t ah1 = *(const uint32_t*)(arH + 8 * HS_ROW_B);
                    uint32_t ah2 = *(const uint32_t*)(arH + 16);
                    uint32_t ah3 = *(const uint32_t*)(arH + 8 * HS_ROW_B + 16);
                    const char* arL = arH + HS_PLANE;
                    uint32_t al0 = *(const uint32_t*)(arL);
                    uint32_t al1 = *(const uint32_t*)(arL + 8 * HS_ROW_B);
                    uint32_t al2 = *(const uint32_t*)(arL + 16);
                    uint32_t al3 = *(const uint32_t*)(arL + 8 * HS_ROW_B + 16);
                    const __half* brH = WtH + nB * WT_ROW_H + k0 + 2 * tg;
                    uint32_t bh0 = *(const uint32_t*)(brH);
                    uint32_t bh1 = *(const uint32_t*)(brH + 8);
                    const __half* brL = WtL + nB * WT_ROW_H + k0 + 2 * tg;
                    uint32_t bl0 = *(const uint32_t*)(brL);
                    uint32_t bl1 = *(const uint32_t*)(brL + 8);
                    mma16816(d0, d1, d2, d3, ah0, ah1, ah2, ah3, bh0, bh1);
                    mma16816(d0, d1, d2, d3, al0, al1, al2, al3, bh0, bh1);
                    mma16816(d0, d1, d2, d3, ah0, ah1, ah2, ah3, bl0, bl1);
                }
            }
            zb[(nt * 8 + 2 * tg) * 64 + mt * 16 + fg] = d0;
            zb[(nt * 8 + 2 * tg + 1) * 64 + mt * 16 + fg] = d1;
            zb[(nt * 8 + 2 * tg) * 64 + mt * 16 + fg + 8] = d2;
            zb[(nt * 8 + 2 * tg + 1) * 64 + mt * 16 + fg + 8] = d3;
            __syncthreads();
            zi = zb[(0 * 4 + uu) * 64 + b] + za[(0 * 64 + b) * 4 + uu];
            zf = zb[(1 * 4 + uu) * 64 + b] + za[(1 * 64 + b) * 4 + uu];
            zg = zb[(2 * 4 + uu) * 64 + b] + za[(2 * 64 + b) * 4 + uu];
            zo = zb[(3 * 4 + uu) * 64 + b] + za[(3 * 64 + b) * 4 + uu];
        }

        float ig = fast_sig(zi);
        float fg2 = fast_sig(zf);
        float gv = fast_tanh(zg);
        float og = fast_sig(zo);
        float cn = fg2 * creg + ig * gv;
        float hn = og * fast_tanh(cn);

        bool msk = t < len;
        if (msk) {
            creg = cn;
            hreg = hn;
        }
        // split h for next step
        {
            __half hhi = __float2half(hreg);
            __half hlo = __float2half(hreg - __half2float(hhi));
            size_t base = (size_t)((t + 1) & 1) * (2 * Bb * Uu) + b * Uu + u;
            hbuf[base] = hhi;
            hbuf[base + Bb * Uu] = hlo;
        }
        H[((size_t)t * Bb + b) * Uu + u] = msk ? hn : 0.f;

        // prefetch A(t+1) so its DRAM latency hides under the barrier spin
        if (t + 1 < Tt)
            a4 = *(const float4*)(A + ((size_t)(t + 1) * Bb + b) * ZN +
                                  uu * Uu + u0);

        grid_sync(bid);
    }
}

// ---------------- host: enqueue the whole pipeline (7 graph nodes) ---------
extern "C" void kernel_launch(void* const* d_in, const int* in_sizes, int n_in,
                              void* d_out, int out_size) {
    const int* tokens = (const int*)d_in[0];
    const int* lengths = (const int*)d_in[1];
    const float* emb = (const float*)d_in[2];
    const float* Wk[3] = {(const float*)d_in[3], (const float*)d_in[6],
                          (const float*)d_in[9]};
    const float* Wr[3] = {(const float*)d_in[4], (const float*)d_in[7],
                          (const float*)d_in[10]};
    const float* bv[3] = {(const float*)d_in[5], (const float*)d_in[8],
                          (const float*)d_in[11]};
    const float* Wd = (const float*)d_in[12];
    const float* bd = (const float*)d_in[13];
    float* out = (float*)d_out;

    float *A, *H;
    __half* hbuf;
    cudaGetSymbolAddress((void**)&A, g_A);
    cudaGetSymbolAddress((void**)&H, g_H);
    cudaGetSymbolAddress((void**)&hbuf, g_hbuf);

    cudaFuncSetAttribute(lstm_layer_kernel,
                         cudaFuncAttributeMaxDynamicSharedMemorySize,
                         STEP_SMEM_BYTES);

    dim3 blk(256);
    dim3 ggrid(ZN / 64, (Bb * Tt) / 128);
    // layer-0 input preactivation: A = emb[tokens] @ Wk0 + b0
    hgemm_kernel<1, 0><<<ggrid, blk>>>(nullptr, tokens, emb, Wk[0], bv[0], A,
                                       Ee, ZN);

    for (int l = 0; l < 3; l++) {
        if (l > 0) {
            // A = H_{l-1} @ Wk_l + b_l   (H fp32 row-major [m][K])
            hgemm_kernel<2, 0><<<ggrid, blk>>>(H, nullptr, nullptr, Wk[l],
                                               bv[l], A, Uu, ZN);
        }
        lstm_layer_kernel<<<NCTA, 256, STEP_SMEM_BYTES>>>(A, Wr[l], lengths,
                                                          hbuf, H);
    }
    // logits = H_2 @ Wd + bd, permuted to [b][t][v]
    hgemm_kernel<2, 1><<<dim3(Vv / 64, (Bb * Tt) / 128), blk>>>(
        H, nullptr, nullptr, Wd, bd, out, Uu, Vv);
}

// round 12
// speedup vs baseline: 2.3754x; 1.2933x over previous
#include <cuda_runtime.h>
#include <cuda_fp16.h>
#include <cstdint>

#define Bb 64
#define Tt 1024
#define Vv 512
#define Ee 256
#define Uu 512
#define ZN 2048  // 4*U
#define NCTA 128
#define NGRP 4          // batch groups
#define GCTA 32         // CTAs per group
#define GB 16           // batches per group

// ---------------- scratch (device globals; no runtime allocation) ----------
__device__ float g_A[(size_t)Tt * Bb * ZN];   // input-side preact [t][b][4U]
__device__ float g_H[(size_t)Tt * Bb * Uu];   // layer stream fp32 [t][b][u]
__device__ __half g_hbuf[2 * 2 * Bb * Uu];    // h split: [buf][plane hi/lo][b][u]
__device__ unsigned g_leafX[NGRP * 4 * 32];   // per-group leaf counters (128B apart)
__device__ unsigned g_rootX[NGRP * 32];       // per-group root counters
__device__ unsigned g_genX[NGRP * 32];        // per-group generation

// ---------------- helpers ---------------------------------------------------
__device__ __forceinline__ unsigned ld_acq(const unsigned* p) {
    unsigned v;
    asm volatile("ld.acquire.gpu.global.u32 %0, [%1];" : "=r"(v) : "l"(p) : "memory");
    return v;
}
__device__ __forceinline__ void cp_async16(unsigned s, const void* g) {
    asm volatile("cp.async.cg.shared.global [%0], [%1], 16;" ::"r"(s), "l"(g)
                 : "memory");
}
__device__ __forceinline__ float fast_tanh(float x) {
    float y;
    asm("tanh.approx.f32 %0, %1;" : "=f"(y) : "f"(x));
    return y;
}
__device__ __forceinline__ float fast_sig(float x) {
    return __fdividef(1.f, 1.f + __expf(-x));
}
__device__ __forceinline__ void mma16816(float& d0, float& d1, float& d2, float& d3,
                                         uint32_t a0, uint32_t a1, uint32_t a2,
                                         uint32_t a3, uint32_t b0, uint32_t b1) {
    asm volatile(
        "mma.sync.aligned.m16n8k16.row.col.f32.f16.f16.f32 "
        "{%0,%1,%2,%3}, {%4,%5,%6,%7}, {%8,%9}, {%0,%1,%2,%3};"
        : "+f"(d0), "+f"(d1), "+f"(d2), "+f"(d3)
        : "r"(a0), "r"(a1), "r"(a2), "r"(a3), "r"(b0), "r"(b1));
}

// ---------------- per-group barrier (32 CTAs: 4 leaves x 8) ----------------
// Monotonic counters; gen[g] bumps only on the 32nd arrival, so the entry
// read of gen is the epoch value for every participant (no reset races).
__device__ __forceinline__ void group_sync(int g, int cg) {
    __threadfence();
    __syncthreads();
    if (threadIdx.x == 0) {
        unsigned* genp = &g_genX[g * 32];
        unsigned g0 = ld_acq(genp);
        unsigned pos = atomicAdd(&g_leafX[(g * 4 + (cg & 3)) * 32], 1);
        if ((pos & 7) == 7) {                  // last of this leaf's 8
            unsigned r = atomicAdd(&g_rootX[g * 32], 1);
            if ((r & 3) == 3) {                // last leaf -> release group
                __threadfence();
                atomicAdd(genp, 1);
            }
        }
        while (ld_acq(genp) == g0) {
        }
    }
    __syncthreads();
}

// ---------------- split-fp16 HMMA GEMM: C = A @ B + bias -------------------
// (verbatim R9 — verified at rel_err 4.1e-5)
template <int AMODE, int OMODE>
__global__ __launch_bounds__(256) void hgemm_kernel(
    const float* __restrict__ Ag, const int* __restrict__ tokens,
    const float* __restrict__ emb, const float* __restrict__ Bg,
    const float* __restrict__ bias, float* __restrict__ C, int K, int Ntot) {
    __shared__ __half AsH[128][40];
    __shared__ __half AsL[128][40];
    __shared__ __half BsH[64][40];
    __shared__ __half BsL[64][40];
    const int tid = threadIdx.x;
    const int m0 = blockIdx.y * 128;
    const int n0 = blockIdx.x * 64;
    const int lane = tid & 31, warp = tid >> 5;
    const int fg = lane >> 2, tg = lane & 3;

    int a_row[4], a_c4[4];
    const float* a_base[4];
#pragma unroll
    for (int i = 0; i < 4; i++) {
        int s = tid + i * 256;
        a_row[i] = s >> 3;
        a_c4[i] = (s & 7) * 4;
        if (AMODE == 1) {
            int gm = m0 + a_row[i];
            int tb = gm & (Bb - 1);
            int tt = gm >> 6;
            int tok = tokens[tb * Tt + tt];
            a_base[i] = emb + (size_t)tok * Ee + a_c4[i];
        } else {
            a_base[i] = Ag + (size_t)(m0 + a_row[i]) * K + a_c4[i];
        }
    }
    int b_kk[2], b_n4[2];
    const float* b_base[2];
#pragma unroll
    for (int i = 0; i < 2; i++) {
        int s = tid + i * 256;
        b_kk[i] = s >> 4;
        b_n4[i] = (s & 15) * 4;
        b_base[i] = Bg + (size_t)b_kk[i] * Ntot + n0 + b_n4[i];
    }

    float acc[8][4];
#pragma unroll
    for (int j = 0; j < 8; j++)
#pragma unroll
        for (int q = 0; q < 4; q++) acc[j][q] = 0.f;

    float4 pa[4], pb[2];
#pragma unroll
    for (int i = 0; i < 4; i++) pa[i] = *(const float4*)a_base[i];
#pragma unroll
    for (int i = 0; i < 2; i++) pb[i] = *(const float4*)b_base[i];

    for (int k0 = 0; k0 < K; k0 += 32) {
#pragma unroll
        for (int i = 0; i < 4; i++) {
            float4 v = pa[i];
            __half2 h01 = __floats2half2_rn(v.x, v.y);
            __half2 h23 = __floats2half2_rn(v.z, v.w);
            float2 f01 = __half22float2(h01);
            float2 f23 = __half22float2(h23);
            __half2 l01 = __floats2half2_rn(v.x - f01.x, v.y - f01.y);
            __half2 l23 = __floats2half2_rn(v.z - f23.x, v.w - f23.y);
            *(__half2*)&AsH[a_row[i]][a_c4[i]] = h01;
            *(__half2*)&AsH[a_row[i]][a_c4[i] + 2] = h23;
            *(__half2*)&AsL[a_row[i]][a_c4[i]] = l01;
            *(__half2*)&AsL[a_row[i]][a_c4[i] + 2] = l23;
        }
#pragma unroll
        for (int i = 0; i < 2; i++) {
            float vv[4] = {pb[i].x, pb[i].y, pb[i].z, pb[i].w};
#pragma unroll
            for (int q = 0; q < 4; q++) {
                int n = b_n4[i] + q;
                __half h = __float2half(vv[q]);
                BsH[n][b_kk[i]] = h;
                BsL[n][b_kk[i]] = __float2half(vv[q] - __half2float(h));
            }
        }
        __syncthreads();

        if (k0 + 32 < K) {
#pragma unroll
            for (int i = 0; i < 4; i++)
                pa[i] = *(const float4*)(a_base[i] + (k0 + 32));
#pragma unroll
            for (int i = 0; i < 2; i++)
                pb[i] = *(const float4*)(b_base[i] + (size_t)(k0 + 32) * Ntot);
        }

#pragma unroll
        for (int k16 = 0; k16 < 2; k16++) {
            const __half* arH = &AsH[warp * 16 + fg][k16 * 16 + 2 * tg];
            uint32_t ah0 = *(const uint32_t*)arH;
            uint32_t ah1 = *(const uint32_t*)(arH + 8 * 40);
            uint32_t ah2 = *(const uint32_t*)(arH + 8);
            uint32_t ah3 = *(const uint32_t*)(arH + 8 * 40 + 8);
            const __half* arL = &AsL[warp * 16 + fg][k16 * 16 + 2 * tg];
            uint32_t al0 = *(const uint32_t*)arL;
            uint32_t al1 = *(const uint32_t*)(arL + 8 * 40);
            uint32_t al2 = *(const uint32_t*)(arL + 8);
            uint32_t al3 = *(const uint32_t*)(arL + 8 * 40 + 8);
#pragma unroll
            for (int j = 0; j < 8; j++) {
                const __half* brH = &BsH[j * 8 + fg][k16 * 16 + 2 * tg];
                uint32_t bh0 = *(const uint32_t*)brH;
                uint32_t bh1 = *(const uint32_t*)(brH + 8);
                const __half* brL = &BsL[j * 8 + fg][k16 * 16 + 2 * tg];
                uint32_t bl0 = *(const uint32_t*)brL;
                uint32_t bl1 = *(const uint32_t*)(brL + 8);
                mma16816(acc[j][0], acc[j][1], acc[j][2], acc[j][3],
                         ah0, ah1, ah2, ah3, bh0, bh1);
                mma16816(acc[j][0], acc[j][1], acc[j][2], acc[j][3],
                         al0, al1, al2, al3, bh0, bh1);
                mma16816(acc[j][0], acc[j][1], acc[j][2], acc[j][3],
                         ah0, ah1, ah2, ah3, bl0, bl1);
            }
        }
        __syncthreads();
    }

    const int rowA = m0 + warp * 16 + fg;
#pragma unroll
    for (int j = 0; j < 8; j++) {
        int col = n0 + j * 8 + 2 * tg;
        float bv0 = bias[col], bv1 = bias[col + 1];
        float r0 = acc[j][0] + bv0, r1 = acc[j][1] + bv1;
        float r2 = acc[j][2] + bv0, r3 = acc[j][3] + bv1;
        if (OMODE == 0) {
            *(float2*)&C[(size_t)rowA * Ntot + col] = make_float2(r0, r1);
            *(float2*)&C[(size_t)(rowA + 8) * Ntot + col] = make_float2(r2, r3);
        } else {
            int t0 = rowA >> 6, b0 = rowA & 63;
            int t1 = (rowA + 8) >> 6, b1 = (rowA + 8) & 63;
            *(float2*)&C[(size_t)b0 * Tt * Vv + (size_t)t0 * Vv + col] =
                make_float2(r0, r1);
            *(float2*)&C[(size_t)b1 * Tt * Vv + (size_t)t1 * Vv + col] =
                make_float2(r2, r3);
        }
    }
}

// ---------------- persistent LSTM layer kernel (batch-grouped) -------------
// 4 groups x 32 CTAs. Group owns 16 batches; CTA owns 16 units (64 z-cols).
// Per step/CTA: z[16b,64n] = h[16b,512k] @ WrSlice[512k,64n] (split-fp16,
// 3 accumulator sets) + A; gates; h exchange only within the group (32KB).
#define HS_ROW_B 1040
#define HS_PLANE (GB * HS_ROW_B)              // 16640
#define WT_OFF (2 * HS_PLANE)                 // 33280
#define WT_ROW_H 520
#define WT_PLANE (64 * HS_ROW_B)              // 66560
#define ZA_OFF (WT_OFF + 2 * WT_PLANE)        // 166400
#define ZB_OFF (ZA_OFF + GB * 64 * 4)         // 170496
#define STEP_SMEM_BYTES (ZB_OFF + 64 * 17 * 4)  // 175120

__global__ __launch_bounds__(256, 1) void lstm_layer_kernel(
    const float* __restrict__ A, const float* __restrict__ Wr,
    const int* __restrict__ lengths, __half* __restrict__ hbuf,
    float* __restrict__ H) {
    extern __shared__ char smc[];
    char* hsH = smc;
    __half* WtH = (__half*)(smc + WT_OFF);
    __half* WtL = (__half*)(smc + WT_OFF + WT_PLANE);
    float* za = (float*)(smc + ZA_OFF);   // [16 b][64 n]
    float* zb = (float*)(smc + ZB_OFF);   // [64 n][17] (padded)
    const int tid = threadIdx.x;
    const int bid = blockIdx.x;
    const int grp = bid >> 5;             // batch group 0..3
    const int cg = bid & 31;              // CTA within group
    const int gb0 = grp * GB;             // first global batch of group
    const int u0 = cg * 16;               // first unit of this CTA
    const unsigned hsH_s = (unsigned)__cvta_generic_to_shared(hsH);
    const unsigned hsL_s = hsH_s + HS_PLANE;

    // prepack Wr slice -> hi/lo planes Wt[n][k], n = gate*16 + unit_local
    for (int i = tid; i < 64 * Uu; i += 256) {
        int n = i & 63, k = i >> 6;
        int gg = n >> 4, ul = n & 15;
        float w = Wr[(size_t)k * ZN + gg * Uu + u0 + ul];
        __half whi = __float2half(w);
        WtH[n * WT_ROW_H + k] = whi;
        WtL[n * WT_ROW_H + k] = __float2half(w - __half2float(whi));
    }

    const int lane = tid & 31, warp = tid >> 5;
    const int fg = lane >> 2, tg = lane & 3;
    // gate / staging ids
    const int b = tid >> 4;               // group-local batch 0..15
    const int ul = tid & 15;              // unit-local 0..15
    const int ag = (tid & 15) >> 2;       // A-staging gate 0..3
    const int aj = tid & 3;               // A-staging chunk 0..3
    const int u = u0 + ul;
    const int len = lengths[gb0 + b];
    float creg = 0.f, hreg = 0.f;

    // prefetch A(0): float4 for (b, gate ag, units u0+4*aj..)
    const float* Abase =
        A + (size_t)(gb0 + b) * ZN + ag * Uu + u0 + aj * 4;
    float4 a4 = *(const float4*)Abase;

    for (int t = 0; t < Tt; t++) {
        float zi, zf, zg, zo;
        if (t == 0) {
            *(float4*)&za[b * 64 + ag * 16 + aj * 4] = a4;
            __syncthreads();
            zi = za[b * 64 + 0 * 16 + ul];
            zf = za[b * 64 + 1 * 16 + ul];
            zg = za[b * 64 + 2 * 16 + ul];
            zo = za[b * 64 + 3 * 16 + ul];
        } else {
            // stage group h (hi+lo) in 4 k-chunks of 128; consume progressively
            const __half* srcH =
                hbuf + (size_t)(t & 1) * (2 * Bb * Uu) + (size_t)gb0 * Uu;
            const __half* srcL = srcH + Bb * Uu;
#pragma unroll
            for (int c = 0; c < 4; c++) {
#pragma unroll
                for (int j = 0; j < 2; j++) {
                    int item = tid + j * 256;        // 0..511
                    int p = item >> 8;               // 0 hi, 1 lo
                    int row = (item >> 4) & 15;
                    int c16 = c * 16 + (item & 15);
                    const __half* s = (p ? srcL : srcH) + row * Uu + c16 * 8;
                    unsigned d = (p ? hsL_s : hsH_s) +
                                 (unsigned)(row * HS_ROW_B + c16 * 16);
                    cp_async16(d, s);
                }
                asm volatile("cp.async.commit_group;" ::: "memory");
            }

            *(float4*)&za[b * 64 + ag * 16 + aj * 4] = a4;

            // 3 accumulator sets -> serial mma chain is 32, not 96
            float hh0 = 0.f, hh1 = 0.f, hh2 = 0.f, hh3 = 0.f;
            float lh0 = 0.f, lh1 = 0.f, lh2 = 0.f, lh3 = 0.f;
            float hl0 = 0.f, hl1 = 0.f, hl2 = 0.f, hl3 = 0.f;
#pragma unroll
            for (int c = 0; c < 4; c++) {
                if (c == 0)
                    asm volatile("cp.async.wait_group 3;" ::: "memory");
                else if (c == 1)
                    asm volatile("cp.async.wait_group 2;" ::: "memory");
                else if (c == 2)
                    asm volatile("cp.async.wait_group 1;" ::: "memory");
                else
                    asm volatile("cp.async.wait_group 0;" ::: "memory");
                __syncthreads();
#pragma unroll
                for (int kt = 0; kt < 8; kt++) {
                    int k0 = c * 128 + kt * 16;
                    const char* arH = hsH + fg * HS_ROW_B + (k0 + 2 * tg) * 2;
                    uint32_t ah0 = *(const uint32_t*)(arH);
                    uint32_t ah1 = *(const uint32_t*)(arH + 8 * HS_ROW_B);
                    uint32_t ah2 = *(const uint32_t*)(arH + 16);
                    uint32_t ah3 = *(const uint32_t*)(arH + 8 * HS_ROW_B + 16);
                    const char* arL = arH + HS_PLANE;
                    uint32_t al0 = *(const uint32_t*)(arL);
                    uint32_t al1 = *(const uint32_t*)(arL + 8 * HS_ROW_B);
                    uint32_t al2 = *(const uint32_t*)(arL + 16);
                    uint32_t al3 = *(const uint32_t*)(arL + 8 * HS_ROW_B + 16);
                    const __half* brH =
                        WtH + (warp * 8 + fg) * WT_ROW_H + k0 + 2 * tg;
                    uint32_t bh0 = *(const uint32_t*)(brH);
                    uint32_t bh1 = *(const uint32_t*)(brH + 8);
                    const __half* brL =
                        WtL + (warp * 8 + fg) * WT_ROW_H + k0 + 2 * tg;
                    uint32_t bl0 = *(const uint32_t*)(brL);
                    uint32_t bl1 = *(const uint32_t*)(brL + 8);
                    mma16816(hh0, hh1, hh2, hh3, ah0, ah1, ah2, ah3, bh0, bh1);
                    mma16816(lh0, lh1, lh2, lh3, al0, al1, al2, al3, bh0, bh1);
                    mma16816(hl0, hl1, hl2, hl3, ah0, ah1, ah2, ah3, bl0, bl1);
                }
            }
            float d0 = (hh0 + lh0) + hl0;
            float d1 = (hh1 + lh1) + hl1;
            float d2 = (hh2 + lh2) + hl2;
            float d3 = (hh3 + lh3) + hl3;
            // scatter D: row m = fg(+8) -> batch, col n = warp*8 + 2*tg(+1)
            zb[(warp * 8 + 2 * tg) * 17 + fg] = d0;
            zb[(warp * 8 + 2 * tg + 1) * 17 + fg] = d1;
            zb[(warp * 8 + 2 * tg) * 17 + fg + 8] = d2;
            zb[(warp * 8 + 2 * tg + 1) * 17 + fg + 8] = d3;
            __syncthreads();
            zi = zb[(0 * 16 + ul) * 17 + b] + za[b * 64 + 0 * 16 + ul];
            zf = zb[(1 * 16 + ul) * 17 + b] + za[b * 64 + 1 * 16 + ul];
            zg = zb[(2 * 16 + ul) * 17 + b] + za[b * 64 + 2 * 16 + ul];
            zo = zb[(3 * 16 + ul) * 17 + b] + za[b * 64 + 3 * 16 + ul];
        }

        float ig = fast_sig(zi);
        float fg2 = fast_sig(zf);
        float gv = fast_tanh(zg);
        float og = fast_sig(zo);
        float cn = fg2 * creg + ig * gv;
        float hn = og * fast_tanh(cn);

        bool msk = t < len;
        if (msk) {
            creg = cn;
            hreg = hn;
        }
        // split h for next step (units contiguous -> 32B/batch/plane)
        {
            __half hhi = __float2half(hreg);
            __half hlo = __float2half(hreg - __half2float(hhi));
            size_t base = (size_t)((t + 1) & 1) * (2 * Bb * Uu) +
                          (size_t)(gb0 + b) * Uu + u;
            hbuf[base] = hhi;
            hbuf[base + Bb * Uu] = hlo;
        }
        H[((size_t)t * Bb + gb0 + b) * Uu + u] = msk ? hn : 0.f;

        // prefetch A(t+1) under the barrier; last step needs no barrier
        if (t + 1 < Tt) {
            a4 = *(const float4*)(Abase + (size_t)(t + 1) * Bb * ZN);
            group_sync(grp, cg);
        }
    }
}

// ---------------- host: enqueue the whole pipeline (7 graph nodes) ---------
extern "C" void kernel_launch(void* const* d_in, const int* in_sizes, int n_in,
                              void* d_out, int out_size) {
    const int* tokens = (const int*)d_in[0];
    const int* lengths = (const int*)d_in[1];
    const float* emb = (const float*)d_in[2];
    const float* Wk[3] = {(const float*)d_in[3], (const float*)d_in[6],
                          (const float*)d_in[9]};
    const float* Wr[3] = {(const float*)d_in[4], (const float*)d_in[7],
                          (const float*)d_in[10]};
    const float* bv[3] = {(const float*)d_in[5], (const float*)d_in[8],
                          (const float*)d_in[11]};
    const float* Wd = (const float*)d_in[12];
    const float* bd = (const float*)d_in[13];
    float* out = (float*)d_out;

    float *A, *H;
    __half* hbuf;
    cudaGetSymbolAddress((void**)&A, g_A);
    cudaGetSymbolAddress((void**)&H, g_H);
    cudaGetSymbolAddress((void**)&hbuf, g_hbuf);

    cudaFuncSetAttribute(lstm_layer_kernel,
                         cudaFuncAttributeMaxDynamicSharedMemorySize,
                         STEP_SMEM_BYTES);

    dim3 blk(256);
    dim3 ggrid(ZN / 64, (Bb * Tt) / 128);
    // layer-0 input preactivation: A = emb[tokens] @ Wk0 + b0
    hgemm_kernel<1, 0><<<ggrid, blk>>>(nullptr, tokens, emb, Wk[0], bv[0], A,
                                       Ee, ZN);

    for (int l = 0; l < 3; l++) {
        if (l > 0) {
            // A = H_{l-1} @ Wk_l + b_l   (H fp32 row-major [m][K])
            hgemm_kernel<2, 0><<<ggrid, blk>>>(H, nullptr, nullptr, Wk[l],
                                               bv[l], A, Uu, ZN);
        }
        lstm_layer_kernel<<<NCTA, 256, STEP_SMEM_BYTES>>>(A, Wr[l], lengths,
                                                          hbuf, H);
    }
    // logits = H_2 @ Wd + bd, permuted to [b][t][v]
    hgemm_kernel<2, 1><<<dim3(Vv / 64, (Bb * Tt) / 128), blk>>>(
        H, nullptr, nullptr, Wd, bd, out, Uu, Vv);
}